// round 2
// baseline (speedup 1.0000x reference)
#include <cuda_runtime.h>

// ---------------- problem constants ----------------
#define NMAX 100000
#define EMAX 3200000
#define F 64

// ---------------- device scratch (no allocs allowed) ----------------
__device__ __align__(16) int   g_deg[NMAX];
__device__ __align__(16) int   g_rowptr[NMAX + 1];
__device__ __align__(16) int   g_cursor[NMAX];
__device__ __align__(16) float g_dinv[NMAX];
__device__ __align__(16) int   g_col[EMAX];
__device__ __align__(16) float g_h [NMAX * F];
__device__ __align__(16) float g_f1[NMAX * F];
__device__ __align__(16) float g_f2[NMAX * F];
__device__ __align__(16) float g_Wa[F * F];
__device__ __align__(16) float g_Wb[F * F];
__device__ __align__(16) float g_Wc[F * F];

// ---------------- kernels ----------------

__global__ void k_zero(int n) {
    int i = blockIdx.x * blockDim.x + threadIdx.x;
    if (i < n) g_deg[i] = 0;
}

__global__ void k_hist(const int* __restrict__ dst, int e) {
    int i = blockIdx.x * blockDim.x + threadIdx.x;
    if (i < e) {
        int d = dst[i];
        if (d >= 0 && d < NMAX) atomicAdd(&g_deg[d], 1);
    }
}

// single-block scan: rowptr (exclusive), cursor copy, dinv
__global__ void k_scan(int n) {
    __shared__ int ssum[1024];
    int t = threadIdx.x;
    int chunk = (n + 1023) >> 10;
    int beg = t * chunk;
    int end = min(n, beg + chunk);
    int s = 0;
    for (int i = beg; i < end; i++) s += g_deg[i];
    ssum[t] = s;
    __syncthreads();
    for (int off = 1; off < 1024; off <<= 1) {
        int v = (t >= off) ? ssum[t - off] : 0;
        __syncthreads();
        ssum[t] += v;
        __syncthreads();
    }
    int running = ssum[t] - s;  // exclusive prefix
    for (int i = beg; i < end; i++) {
        g_rowptr[i] = running;
        g_cursor[i] = running;
        int d = g_deg[i];
        g_dinv[i] = rsqrtf((float)(d < 1 ? 1 : d));
        running += d;
    }
    if (t == 1023) g_rowptr[n] = ssum[1023];
}

__global__ void k_fill(const int* __restrict__ src, const int* __restrict__ dst, int e) {
    int i = blockIdx.x * blockDim.x + threadIdx.x;
    if (i < e) {
        int d = dst[i];
        if (d < 0 || d >= NMAX) return;
        int pos = atomicAdd(&g_cursor[d], 1);
        if (pos >= 0 && pos < EMAX) g_col[pos] = src[i];
    }
}

// Fold the theta-weighted concat into three combined 64x64 weight blocks:
//   y = relu( h@Wa + f1@Wb + f2@Wc + b3 )
// Wa = 3*W3[0:64]; Wb = -3*W3[0:64] + 3*W3[64:128];
// Wc = 0.75*W3[0:64] - 1.5*W3[64:128] + 0.75*W3[128:192]
__global__ void k_wcomb(const float* __restrict__ W3) {
    int i = blockIdx.x * blockDim.x + threadIdx.x;
    if (i < F * F) {
        float a = W3[i];
        float b = W3[F * F + i];
        float c = W3[2 * F * F + i];
        g_Wa[i] = 3.0f * a;
        g_Wb[i] = -3.0f * a + 3.0f * b;
        g_Wc[i] = 0.75f * a - 1.5f * b + 0.75f * c;
    }
}

// Fused: h = relu(relu(X@W1+b1)@W2+b2), one thread per node row
__global__ void __launch_bounds__(128)
k_mlp(const float* __restrict__ X,
      const float* __restrict__ W1, const float* __restrict__ b1,
      const float* __restrict__ W2, const float* __restrict__ b2, int n) {
    __shared__ float4 w1s[F * 16];
    __shared__ float4 w2s[F * 16];
    __shared__ float  b1s[F], b2s[F];
    int tid = threadIdx.x;
    for (int i = tid; i < F * 16; i += 128) {
        w1s[i] = ((const float4*)W1)[i];
        w2s[i] = ((const float4*)W2)[i];
    }
    if (tid < F) { b1s[tid] = b1[tid]; b2s[tid] = b2[tid]; }
    __syncthreads();

    int node = blockIdx.x * 128 + tid;
    if (node >= n) return;

    const float4* xp = (const float4*)(X + (size_t)node * F);

    float h1[F];
#pragma unroll
    for (int j = 0; j < F; j++) h1[j] = b1s[j];

    // GEMM1: k-outer (x streamed), j-inner unrolled (h1 static indices)
    for (int k4 = 0; k4 < 16; k4++) {
        float4 xv = __ldg(xp + k4);
#pragma unroll
        for (int c = 0; c < 4; c++) {
            float xk = (c == 0) ? xv.x : (c == 1) ? xv.y : (c == 2) ? xv.z : xv.w;
            int k = k4 * 4 + c;
#pragma unroll
            for (int j4 = 0; j4 < 16; j4++) {
                float4 w = w1s[k * 16 + j4];
                h1[4 * j4 + 0] = fmaf(xk, w.x, h1[4 * j4 + 0]);
                h1[4 * j4 + 1] = fmaf(xk, w.y, h1[4 * j4 + 1]);
                h1[4 * j4 + 2] = fmaf(xk, w.z, h1[4 * j4 + 2]);
                h1[4 * j4 + 3] = fmaf(xk, w.w, h1[4 * j4 + 3]);
            }
        }
    }
#pragma unroll
    for (int j = 0; j < F; j++) h1[j] = fmaxf(h1[j], 0.0f);

    // GEMM2: j-outer, k-inner unrolled (h1[k] static indices)
    float4* hp = (float4*)(g_h + (size_t)node * F);
    for (int j4 = 0; j4 < 16; j4++) {
        float4 acc = make_float4(b2s[4 * j4], b2s[4 * j4 + 1], b2s[4 * j4 + 2], b2s[4 * j4 + 3]);
#pragma unroll
        for (int k = 0; k < F; k++) {
            float4 w = w2s[k * 16 + j4];
            float hk = h1[k];
            acc.x = fmaf(hk, w.x, acc.x);
            acc.y = fmaf(hk, w.y, acc.y);
            acc.z = fmaf(hk, w.z, acc.z);
            acc.w = fmaf(hk, w.w, acc.w);
        }
        acc.x = fmaxf(acc.x, 0.0f);
        acc.y = fmaxf(acc.y, 0.0f);
        acc.z = fmaxf(acc.z, 0.0f);
        acc.w = fmaxf(acc.w, 0.0f);
        hp[j4] = acc;
    }
}

// Laplacian: out[d] = f[d] - dinv[d] * sum_{s in N_in(d)} dinv[s]*f[s]
// one warp per node, float2 per lane (64 feats)
// pass 0: g_h -> g_f1 ; pass 1: g_f1 -> g_f2
__global__ void __launch_bounds__(256)
k_lap(int pass, int n) {
    const float* fin  = (pass == 0) ? g_h  : g_f1;
    float*       fout = (pass == 0) ? g_f1 : g_f2;

    int warp = threadIdx.x >> 5;
    int lane = threadIdx.x & 31;
    int node = blockIdx.x * 8 + warp;
    if (node >= n) return;

    int beg = __ldg(&g_rowptr[node]);
    int end = __ldg(&g_rowptr[node + 1]);

    const float2* fp = (const float2*)fin;

    // start self-row load early; latency overlaps the gather loop
    float  dd = __ldg(&g_dinv[node]);
    float2 fd = __ldg(&fp[(size_t)node * 32 + lane]);

    float ax = 0.0f, ay = 0.0f;

    for (int base = beg; base < end; base += 32) {
        int idx = base + lane;
        int   c  = 0;
        float dv = 0.0f;
        if (idx < end) {
            c  = __ldg(&g_col[idx]);
            dv = __ldg(&g_dinv[c]);
        }
        int cnt = min(32, end - base);
#pragma unroll 4
        for (int i = 0; i < cnt; i++) {
            int   s  = __shfl_sync(0xffffffffu, c,  i);
            float ds = __shfl_sync(0xffffffffu, dv, i);
            float2 v = __ldg(&fp[(size_t)s * 32 + lane]);
            ax = fmaf(ds, v.x, ax);
            ay = fmaf(ds, v.y, ay);
        }
    }
    float2 o;
    o.x = fd.x - dd * ax;
    o.y = fd.y - dd * ay;
    ((float2*)fout)[(size_t)node * 32 + lane] = o;
}

// Fused tail: y = relu(h@Wa + f1@Wb + f2@Wc + b3); out = y@W4 + b4
__global__ void __launch_bounds__(128)
k_final(const float* __restrict__ b3, const float* __restrict__ W4,
        const float* __restrict__ b4, float* __restrict__ out, int n) {
    __shared__ float4 was[F * 16];
    __shared__ float4 wbs[F * 16];
    __shared__ float4 wcs[F * 16];  // 48KB static, at the limit
    int tid = threadIdx.x;
    for (int i = tid; i < F * 16; i += 128) {
        was[i] = ((const float4*)g_Wa)[i];
        wbs[i] = ((const float4*)g_Wb)[i];
        wcs[i] = ((const float4*)g_Wc)[i];
    }
    __syncthreads();

    int node = blockIdx.x * 128 + tid;
    if (node >= n) return;

    float y[F];
#pragma unroll
    for (int j = 0; j < F; j++) y[j] = __ldg(b3 + j);

    const float4* hp  = (const float4*)(g_h  + (size_t)node * F);
    const float4* f1p = (const float4*)(g_f1 + (size_t)node * F);
    const float4* f2p = (const float4*)(g_f2 + (size_t)node * F);

    for (int k4 = 0; k4 < 16; k4++) {
        float4 hv  = __ldg(hp  + k4);
        float4 f1v = __ldg(f1p + k4);
        float4 f2v = __ldg(f2p + k4);
#pragma unroll
        for (int c = 0; c < 4; c++) {
            float hk  = (c == 0) ? hv.x  : (c == 1) ? hv.y  : (c == 2) ? hv.z  : hv.w;
            float f1k = (c == 0) ? f1v.x : (c == 1) ? f1v.y : (c == 2) ? f1v.z : f1v.w;
            float f2k = (c == 0) ? f2v.x : (c == 1) ? f2v.y : (c == 2) ? f2v.z : f2v.w;
            int k = k4 * 4 + c;
#pragma unroll
            for (int j4 = 0; j4 < 16; j4++) {
                float4 wa = was[k * 16 + j4];
                float4 wb = wbs[k * 16 + j4];
                float4 wc = wcs[k * 16 + j4];
                y[4 * j4 + 0] = fmaf(hk, wa.x, fmaf(f1k, wb.x, fmaf(f2k, wc.x, y[4 * j4 + 0])));
                y[4 * j4 + 1] = fmaf(hk, wa.y, fmaf(f1k, wb.y, fmaf(f2k, wc.y, y[4 * j4 + 1])));
                y[4 * j4 + 2] = fmaf(hk, wa.z, fmaf(f1k, wb.z, fmaf(f2k, wc.z, y[4 * j4 + 2])));
                y[4 * j4 + 3] = fmaf(hk, wa.w, fmaf(f1k, wb.w, fmaf(f2k, wc.w, y[4 * j4 + 3])));
            }
        }
    }

    float o0 = __ldg(b4 + 0);
    float o1 = __ldg(b4 + 1);
#pragma unroll
    for (int j = 0; j < F; j++) {
        float yj = fmaxf(y[j], 0.0f);
        o0 = fmaf(yj, __ldg(W4 + j * 2 + 0), o0);
        o1 = fmaf(yj, __ldg(W4 + j * 2 + 1), o1);
    }
    ((float2*)out)[node] = make_float2(o0, o1);
}

// ---------------- launcher ----------------
extern "C" void kernel_launch(void* const* d_in, const int* in_sizes, int n_in,
                              void* d_out, int out_size) {
    const float* in_feat = (const float*)d_in[0];
    const int*   src     = (const int*)d_in[1];
    const int*   dst     = (const int*)d_in[2];
    const float* W1 = (const float*)d_in[3];
    const float* b1 = (const float*)d_in[4];
    const float* W2 = (const float*)d_in[5];
    const float* b2 = (const float*)d_in[6];
    const float* W3 = (const float*)d_in[7];
    const float* b3 = (const float*)d_in[8];
    const float* W4 = (const float*)d_in[9];
    const float* b4 = (const float*)d_in[10];

    int n = in_sizes[0] / F;
    if (n > NMAX) n = NMAX;
    int e = in_sizes[1];
    if (e > EMAX) e = EMAX;

    k_zero<<<(n + 255) / 256, 256>>>(n);
    k_hist<<<(e + 255) / 256, 256>>>(dst, e);
    k_scan<<<1, 1024>>>(n);
    k_fill<<<(e + 255) / 256, 256>>>(src, dst, e);
    k_wcomb<<<(F * F + 255) / 256, 256>>>(W3);
    k_mlp<<<(n + 127) / 128, 128>>>(in_feat, W1, b1, W2, b2, n);
    k_lap<<<(n + 7) / 8, 256>>>(0, n);
    k_lap<<<(n + 7) / 8, 256>>>(1, n);
    k_final<<<(n + 127) / 128, 128>>>(b3, W4, b4, (float*)d_out, n);
}